// round 11
// baseline (speedup 1.0000x reference)
#include <cuda_runtime.h>
#include <math.h>
#include <stdint.h>

#define MAXT_C 10000
#define PADT   10240     // NTH * ELEMS, zero-padded so phase-2 float4 reloads are unguarded
#define MAXB_C 4096
#define TCHUNK 16
#define NTH    512
#define ELEMS  20        // ceil(10000/512)
#define GRIDY  74        // persistent grid: 2 x 74 = 148 blocks = 1 wave @ 1 block/SM
// Input-independent screen: T2_t <= T2_0 = q0/(1-q0), q0 = exp(INIT_LOGP) = 1e-3
// => death requires u2 > exp(log(1e-12)*T2_0) - 1e-12 ~= 0.97267. 0.9720 is safely below.
#define U2MIN_GLOB 0.9720f

// Scratch (static __device__ arrays: no allocation allowed)
__device__ float   g_f[PADT];            // exp(acts[t]), zero past T (producer-written)
__device__ float   g_c[PADT];            // LOG_GAMMA + log(1 - f), zero past T
__device__ float   g_T2[MAXT_C];         // per-step death threshold: exp(logit_t) - eps
__device__ double  g_prefix[MAXT_C + 1]; // prefix[k] = sum_{t<k} w_t
__device__ int     g_deathX[MAXB_C];     // atomicMax of (T - death_t); 0 = alive. Zero-init OK.
__device__ int     g_tcut;               // no deaths possible for t >= g_tcut
__device__ int     g_flag;               // phase-2 publication flag    (reset by last block)
__device__ int     g_done;               // completion counter          (reset by last block)

// ---------------------------------------------------------------------------
// Exclusive block-wide scan (blockDim.x == NTH), fp64.
__device__ __forceinline__ double block_scan_excl(double v, double& total, double* s_warp) {
    const unsigned FULL = 0xffffffffu;
    int lane = threadIdx.x & 31;
    int w    = threadIdx.x >> 5;
    const int NW = NTH / 32;
    double inc = v;
#pragma unroll
    for (int o = 1; o < 32; o <<= 1) {
        double n = __shfl_up_sync(FULL, inc, o);
        if (lane >= o) inc += n;
    }
    double exc = __shfl_up_sync(FULL, inc, 1);
    if (lane == 0) exc = 0.0;
    if (lane == 31) s_warp[w] = inc;
    __syncthreads();
    if (w == 0 && lane < NW) {
        double i2 = s_warp[lane];
#pragma unroll
        for (int o = 1; o < NW; o <<= 1) {
            double n = __shfl_up_sync((1u << NW) - 1u, i2, o);
            if (lane >= o) i2 += n;
        }
        double e2 = __shfl_up_sync((1u << NW) - 1u, i2, 1);
        if (lane == 0) e2 = 0.0;
        s_warp[lane] = e2;
        if (lane == NW - 1) s_warp[NW] = i2;
    }
    __syncthreads();
    exc += s_warp[w];
    total = s_warp[NW];
    __syncthreads();
    return exc;
}

// exp(x) for tiny |x| without MUFU; fallback for the rare large case.
__device__ __forceinline__ float exp_tiny(float x) {
    if (fabsf(x) < 0.03f)
        return 1.0f + x * (1.0f + x * (0.5f + x * (1.0f / 6.0f)));
    return __expf(x);
}

// ---------------------------------------------------------------------------
// Producer body (block 0 only). Pass 1 computes f/c inline from acts (no
// separate phase-1 sync); later passes reload g_f/g_c as float4 (no spills).
__device__ void scanbases_body(const float* __restrict__ acts, int T) {
    __shared__ double s_warp[NTH / 32 + 1];
    __shared__ int s_imax[NTH / 32];
    int tid = threadIdx.x;
    int seg = tid * ELEMS;
    const float4* f4 = (const float4*)g_f;
    const float4* c4 = (const float4*)g_c;

    const float LOG_GAMMA_F = (float)log(1.02);
    const float ALPHA_F     = (float)(log(0.99) / 1000.0);
    const float INIT_LOGW_F = (float)log(0.248);
    const float INIT_LOGP_F = (float)log(0.001);

    // pass 1: f,c from acts; store (pad zeros); segment c-sum
    float csum = 0.0f;
#pragma unroll
    for (int j = 0; j < ELEMS; j++) {
        int i = seg + j;
        float fv = 0.0f, cv = 0.0f;
        if (i < T) {
            fv = __expf(acts[i]);
            cv = LOG_GAMMA_F + __logf(1.0f - fv);
        }
        g_f[i] = fv;
        g_c[i] = cv;
        csum += cv;
    }
    double tot;
    double Wbase_d = block_scan_excl((double)csum, tot, s_warp) + (double)INIT_LOGW_F;
    float  Wbase   = (float)Wbase_d;

    // pass 2: df chain -> segment dfsum (pad f=0 contributes 0)
    float dfsum = 0.0f;
    {
        float ew = __expf(Wbase);
#pragma unroll
        for (int k = 0; k < ELEMS / 4; k++) {
            float4 f = f4[(seg >> 2) + k];
            dfsum += ALPHA_F * f.x * ew; ew *= 1.02f * (1.0f - f.x);
            dfsum += ALPHA_F * f.y * ew; ew *= 1.02f * (1.0f - f.y);
            dfsum += ALPHA_F * f.z * ew; ew *= 1.02f * (1.0f - f.z);
            dfsum += ALPHA_F * f.w * ew; ew *= 1.02f * (1.0f - f.w);
        }
    }
    double Pbase_d = block_scan_excl((double)dfsum, tot, s_warp) + (double)INIT_LOGP_F;

    // pass 3: thresholds (q chain), tcut, wv chain -> wvsum
    float wvsum = 0.0f;
    int tmax = 0;
    {
        float ew = __expf(Wbase);
        float q  = __expf((float)Pbase_d);
        float v  = __expf(Wbase * 0.001f);
#pragma unroll
        for (int k = 0; k < ELEMS / 4; k++) {
            float4 f = f4[(seg >> 2) + k];
            float4 c = c4[(seg >> 2) + k];
#pragma unroll
            for (int u = 0; u < 4; u++) {
                float fe = (u == 0) ? f.x : (u == 1) ? f.y : (u == 2) ? f.z : f.w;
                float ce = (u == 0) ? c.x : (u == 1) ? c.y : (u == 2) ? c.z : c.w;
                int i = seg + k * 4 + u;
                v *= exp_tiny(ce * 0.001f);
                if (i < T) {
                    float thr = q * (1.0f + q + q * q);     // = q/(1-q), q <= 1e-3
                    g_T2[i] = thr - 1e-12f;
                    if (q >= 1.4e-11f) tmax = i + 1;        // logit >= -25 (noise <= ~20)
                    wvsum += v;
                }
                float df = ALPHA_F * fe * ew;
                q = (q >= 1e-13f) ? q * exp_tiny(df) : 0.0f;
                ew *= 1.02f * (1.0f - fe);
            }
        }
    }
    double Sbase = block_scan_excl((double)wvsum, tot, s_warp);

    // pass 4: recompute wv chain, write exclusive prefix
    {
        float v = __expf(Wbase * 0.001f);
        float ls = 0.0f;
#pragma unroll
        for (int k = 0; k < ELEMS / 4; k++) {
            float4 c = c4[(seg >> 2) + k];
#pragma unroll
            for (int u = 0; u < 4; u++) {
                float ce = (u == 0) ? c.x : (u == 1) ? c.y : (u == 2) ? c.z : c.w;
                int i = seg + k * 4 + u;
                v *= exp_tiny(ce * 0.001f);
                if (i < T) {
                    g_prefix[i] = Sbase + (double)ls;
                    ls += v;
                }
            }
        }
    }
    if (tid == 0) g_prefix[T] = tot;

    // tcut block max-reduce
#pragma unroll
    for (int o = 16; o > 0; o >>= 1) tmax = max(tmax, __shfl_down_sync(0xffffffffu, tmax, o));
    if ((tid & 31) == 0) s_imax[tid >> 5] = tmax;
    __syncthreads();
    if (tid < NTH / 32) {
        int v = s_imax[tid];
#pragma unroll
        for (int o = (NTH / 64); o > 0; o >>= 1)
            v = max(v, __shfl_down_sync((1u << (NTH / 32)) - 1u, v, o));
        if (tid == 0) g_tcut = v;
    }
}

// ---------------------------------------------------------------------------
__device__ __forceinline__ void load_screen(unsigned m[4], const float4* __restrict__ u2v,
                                            int tstart, int b4, int T, int B) {
    float4 v[TCHUNK];
#pragma unroll
    for (int t = 0; t < TCHUNK; t++)
        v[t] = (tstart + t < T) ? u2v[((size_t)(tstart + t) * B + b4) >> 2]
                                : make_float4(0.f, 0.f, 0.f, 0.f);
    m[0] = m[1] = m[2] = m[3] = 0;
#pragma unroll
    for (int t = 0; t < TCHUNK; t++) {
        if (v[t].x > U2MIN_GLOB) m[0] |= 1u << t;
        if (v[t].y > U2MIN_GLOB) m[1] |= 1u << t;
        if (v[t].z > U2MIN_GLOB) m[2] |= 1u << t;
        if (v[t].w > U2MIN_GLOB) m[3] |= 1u << t;
    }
}

// Resolve one lane's candidates. No break: all loads issue in parallel.
__device__ __forceinline__ void resolve_lane(unsigned m, int tstart, int b,
                                             const float* __restrict__ u1,
                                             const float* __restrict__ u2,
                                             int T, int B) {
    if (!m) return;
    if (T - g_deathX[b] <= tstart) return;     // already dead earlier
    const float EPSF = 1e-12f;
    int best = -1;
    while (m) {
        int t = __ffs(m) - 1;
        m &= m - 1;
        size_t idx = (size_t)(tstart + t) * B + b;
        float la = __logf(u2[idx] + EPSF);     // L1 hit (chunk just streamed)
        float lb = __logf(u1[idx] + EPSF);
        if (la > g_T2[tstart + t] * lb && best < 0) best = t;
    }
    if (best >= 0) atomicMax(&g_deathX[b], T - (tstart + best));
}

// ---------------------------------------------------------------------------
// Single fused kernel. Grid = (ceil(B/2048), GRIDY) = 148 blocks, 1 block/SM,
// all resident in wave 1 => internal flag-spin is deadlock-free.
__global__ void __launch_bounds__(NTH, 1)
k_all(const float* __restrict__ acts, const float* __restrict__ u1,
      const float* __restrict__ u2, float* __restrict__ out,
      int T, int B, int nblocks) {
    int tid = threadIdx.x;
    bool producer = (blockIdx.x == 0 && blockIdx.y == 0);
    int b4 = (blockIdx.x * NTH + tid) * 4;
    bool lanes_ok = (b4 + 3 < B);
    const float4* u2v = (const float4*)u2;
    int tstart0 = blockIdx.y * TCHUNK;

    unsigned m[4] = {0, 0, 0, 0};

    if (producer) {
        // Phase A: scan bases / thresholds / prefix (nothing waits on others)
        scanbases_body(acts, T);
        __syncthreads();
        if (tid == 0) { __threadfence(); atomicExch(&g_flag, 1); }
        __syncthreads();
        if (lanes_ok) load_screen(m, u2v, tstart0, b4, T, B);
    } else {
        // Phase B (overlapped with A): stream own chunk, screen with the
        // input-independent constant bound. Only resolution needs the flag.
        if (lanes_ok) load_screen(m, u2v, tstart0, b4, T, B);
        if (tid == 0) {
            volatile int* vf = &g_flag;
            while (*vf == 0) __nanosleep(32);
        }
        __syncthreads();
        __threadfence();
    }

    // Resolve first chunk (exact test rejects anything past tcut on its own)
    if (lanes_ok) {
#pragma unroll
        for (int l = 0; l < 4; l++)
            resolve_lane(m[l], tstart0, b4 + l, u1, u2, T, B);
    }

    // Later chunks (only if tcut > GRIDY*TCHUNK; none for this instance)
    int tcut = g_tcut;
    for (int chunk = blockIdx.y + GRIDY; chunk * TCHUNK < tcut; chunk += GRIDY) {
        if (lanes_ok) {
            unsigned mm[4];
            load_screen(mm, u2v, chunk * TCHUNK, b4, T, B);
#pragma unroll
            for (int l = 0; l < 4; l++)
                resolve_lane(mm[l], chunk * TCHUNK, b4 + l, u1, u2, T, B);
        }
    }

    // Completion: last block reduces, then resets state for the next replay.
    __threadfence();
    __shared__ int lastFlag;
    if (tid == 0) lastFlag = (atomicAdd(&g_done, 1) == nblocks - 1);
    __syncthreads();
    if (!lastFlag) return;

    __shared__ double s_red[NTH / 32];
    double s = 0.0;
    for (int i = tid; i < B; i += NTH)
        s += g_prefix[T - g_deathX[i]];        // deathX=0 (alive) -> prefix[T]
#pragma unroll
    for (int o = 16; o > 0; o >>= 1) s += __shfl_down_sync(0xffffffffu, s, o);
    if ((tid & 31) == 0) s_red[tid >> 5] = s;
    __syncthreads();
    if (tid < NTH / 32) {
        double v = s_red[tid];
#pragma unroll
        for (int o = NTH / 64; o > 0; o >>= 1)
            v += __shfl_down_sync((1u << (NTH / 32)) - 1u, v, o);
        if (tid == 0) out[0] = (float)(v / (double)B);
    }
    __syncthreads();
    for (int i = tid; i < B; i += NTH) g_deathX[i] = 0;   // reset for next replay
    if (tid == 0) { g_flag = 0; g_done = 0; }
}

extern "C" void kernel_launch(void* const* d_in, const int* in_sizes, int n_in,
                              void* d_out, int out_size) {
    const float* acts = (const float*)d_in[0];
    const float* u1   = (const float*)d_in[1];
    const float* u2   = (const float*)d_in[2];
    int T = in_sizes[0];
    int B = (T > 0) ? (in_sizes[1] / T) : 0;

    int gx = (B + NTH * 4 - 1) / (NTH * 4);           // 2 for B=4096
    dim3 grid(gx, GRIDY);                             // 148 blocks total
    int nblocks = gx * GRIDY;
    k_all<<<grid, NTH>>>(acts, u1, u2, (float*)d_out, T, B, nblocks);
}

// round 12
// speedup vs baseline: 1.2737x; 1.2737x over previous
#include <cuda_runtime.h>
#include <math.h>
#include <stdint.h>

#define MAXT_C 10000
#define PADT   10240     // NTH * ELEMS, zero-padded so float4 reloads are unguarded
#define MAXB_C 4096
#define TCHUNK 16
#define NTH    512
#define ELEMS  20        // ceil(10000/512)
#define NCHUNK ((MAXT_C + TCHUNK - 1) / TCHUNK)
#define GRIDY  74        // persistent grid: 2 x 74 = 148 blocks = 1 wave @ 1 block/SM

// Scratch (static __device__ arrays: no allocation allowed)
__device__ float   g_f[PADT];            // exp(acts[t]), zero past T
__device__ float   g_c[PADT];            // LOG_GAMMA + log(1 - f), zero past T
__device__ float   g_T2[MAXT_C];         // per-step death threshold: exp(logit_t) - eps
__device__ float   g_u2min[NCHUNK];      // per-chunk screen: death impossible unless u2 > this
__device__ double  g_prefix[MAXT_C + 1]; // prefix[k] = sum_{t<k} w_t
__device__ int     g_deathX[MAXB_C];     // atomicMax of (T - death_t); 0 = alive (zero-init OK)
__device__ int     g_tcut;               // no deaths possible for t >= g_tcut
__device__ int     g_elemdone;           // phase-1 completion counter  (reset by last block)
__device__ int     g_flag;               // phase-2 publication flag    (reset by last block)
__device__ int     g_done;               // completion counter          (reset by last block)

// ---------------------------------------------------------------------------
// Exclusive block-wide scan, fp32 (fast path: SHFL+FADD, lat ~30/level).
__device__ __forceinline__ float block_scan_excl_f32(float v, float& total, float* s_warp) {
    const unsigned FULL = 0xffffffffu;
    int lane = threadIdx.x & 31;
    int w    = threadIdx.x >> 5;
    const int NW = NTH / 32;
    float inc = v;
#pragma unroll
    for (int o = 1; o < 32; o <<= 1) {
        float n = __shfl_up_sync(FULL, inc, o);
        if (lane >= o) inc += n;
    }
    float exc = __shfl_up_sync(FULL, inc, 1);
    if (lane == 0) exc = 0.0f;
    if (lane == 31) s_warp[w] = inc;
    __syncthreads();
    if (w == 0 && lane < NW) {
        float i2 = s_warp[lane];
#pragma unroll
        for (int o = 1; o < NW; o <<= 1) {
            float n = __shfl_up_sync((1u << NW) - 1u, i2, o);
            if (lane >= o) i2 += n;
        }
        float e2 = __shfl_up_sync((1u << NW) - 1u, i2, 1);
        if (lane == 0) e2 = 0.0f;
        s_warp[lane] = e2;
        if (lane == NW - 1) s_warp[NW] = i2;
    }
    __syncthreads();
    exc += s_warp[w];
    total = s_warp[NW];
    __syncthreads();
    return exc;
}

// Exclusive block-wide scan, fp64 (used only for the output-feeding S scan).
__device__ __forceinline__ double block_scan_excl_f64(double v, double& total, double* s_warp) {
    const unsigned FULL = 0xffffffffu;
    int lane = threadIdx.x & 31;
    int w    = threadIdx.x >> 5;
    const int NW = NTH / 32;
    double inc = v;
#pragma unroll
    for (int o = 1; o < 32; o <<= 1) {
        double n = __shfl_up_sync(FULL, inc, o);
        if (lane >= o) inc += n;
    }
    double exc = __shfl_up_sync(FULL, inc, 1);
    if (lane == 0) exc = 0.0;
    if (lane == 31) s_warp[w] = inc;
    __syncthreads();
    if (w == 0 && lane < NW) {
        double i2 = s_warp[lane];
#pragma unroll
        for (int o = 1; o < NW; o <<= 1) {
            double n = __shfl_up_sync((1u << NW) - 1u, i2, o);
            if (lane >= o) i2 += n;
        }
        double e2 = __shfl_up_sync((1u << NW) - 1u, i2, 1);
        if (lane == 0) e2 = 0.0;
        s_warp[lane] = e2;
        if (lane == NW - 1) s_warp[NW] = i2;
    }
    __syncthreads();
    exc += s_warp[w];
    total = s_warp[NW];
    __syncthreads();
    return exc;
}

// exp(x) for tiny |x| without MUFU; fallback for the rare large case.
__device__ __forceinline__ float exp_tiny(float x) {
    if (fabsf(x) < 0.03f)
        return 1.0f + x * (1.0f + x * (0.5f + x * (1.0f / 6.0f)));
    return __expf(x);
}

// ---------------------------------------------------------------------------
// Phase 2 body (block 0 only). No per-thread arrays (float4 reloads, no spills).
__device__ void scanbases_body(int T) {
    __shared__ float  s_warpf[NTH / 32 + 1];
    __shared__ double s_warpd[NTH / 32 + 1];
    __shared__ int s_imax[NTH / 32];
    int tid = threadIdx.x;
    int seg = tid * ELEMS;
    const float4* f4 = (const float4*)g_f;   // seg*4 bytes is 16B-aligned (80*tid)
    const float4* c4 = (const float4*)g_c;

    const float ALPHA_F     = (float)(log(0.99) / 1000.0);
    const float INIT_LOGW_F = (float)log(0.248);
    const float INIT_LOGP_F = (float)log(0.001);

    // pass 1: segment c-sum (fp32 scan)
    float csum = 0.0f;
#pragma unroll
    for (int k = 0; k < ELEMS / 4; k++) {
        float4 c = c4[(seg >> 2) + k];
        csum += c.x + c.y + c.z + c.w;
    }
    float ctot;
    float Wbase = block_scan_excl_f32(csum, ctot, s_warpf) + INIT_LOGW_F;

    // pass 2: df chain -> segment dfsum (fp32 scan; pad f=0 contributes 0)
    float dfsum = 0.0f;
    {
        float ew = __expf(Wbase);
#pragma unroll
        for (int k = 0; k < ELEMS / 4; k++) {
            float4 f = f4[(seg >> 2) + k];
            dfsum += ALPHA_F * f.x * ew; ew *= 1.02f * (1.0f - f.x);
            dfsum += ALPHA_F * f.y * ew; ew *= 1.02f * (1.0f - f.y);
            dfsum += ALPHA_F * f.z * ew; ew *= 1.02f * (1.0f - f.z);
            dfsum += ALPHA_F * f.w * ew; ew *= 1.02f * (1.0f - f.w);
        }
    }
    float dtot;
    float Pbase = block_scan_excl_f32(dfsum, dtot, s_warpf) + INIT_LOGP_F;

    // pass 3: thresholds (q chain), screen, tcut, wv chain -> wvsum
    float wvsum = 0.0f;
    int tmax = 0;
    {
        float ew = __expf(Wbase);
        float q  = __expf(Pbase);
        float v  = __expf(Wbase * 0.001f);
#pragma unroll
        for (int k = 0; k < ELEMS / 4; k++) {
            float4 f = f4[(seg >> 2) + k];
            float4 c = c4[(seg >> 2) + k];
#pragma unroll
            for (int u = 0; u < 4; u++) {
                float fe = (u == 0) ? f.x : (u == 1) ? f.y : (u == 2) ? f.z : f.w;
                float ce = (u == 0) ? c.x : (u == 1) ? c.y : (u == 2) ? c.z : c.w;
                int i = seg + k * 4 + u;
                v *= exp_tiny(ce * 0.001f);
                if (i < T) {
                    float thr = q * (1.0f + q + q * q);     // = q/(1-q), q <= 1e-3
                    float T2  = thr - 1e-12f;
                    g_T2[i] = T2;
                    if ((i & (TCHUNK - 1)) == 0)            // T2 monotone decreasing
                        g_u2min[i / TCHUNK] = exp_tiny(-27.64f * T2) * (1.0f - 1e-5f);
                    if (q >= 1.4e-11f) tmax = i + 1;        // logit >= -25 (noise <= ~20)
                    wvsum += v;
                }
                float df = ALPHA_F * fe * ew;
                q = (q >= 1e-13f) ? q * exp_tiny(df) : 0.0f;
                ew *= 1.02f * (1.0f - fe);
            }
        }
    }
    double tot;
    double Sbase = block_scan_excl_f64((double)wvsum, tot, s_warpd);

    // pass 4: recompute wv chain, write exclusive prefix
    {
        float v = __expf(Wbase * 0.001f);
        float ls = 0.0f;
#pragma unroll
        for (int k = 0; k < ELEMS / 4; k++) {
            float4 c = c4[(seg >> 2) + k];
#pragma unroll
            for (int u = 0; u < 4; u++) {
                float ce = (u == 0) ? c.x : (u == 1) ? c.y : (u == 2) ? c.z : c.w;
                int i = seg + k * 4 + u;
                v *= exp_tiny(ce * 0.001f);
                if (i < T) {
                    g_prefix[i] = Sbase + (double)ls;
                    ls += v;
                }
            }
        }
    }
    if (tid == 0) g_prefix[T] = tot;

    // tcut block max-reduce
#pragma unroll
    for (int o = 16; o > 0; o >>= 1) tmax = max(tmax, __shfl_down_sync(0xffffffffu, tmax, o));
    if ((tid & 31) == 0) s_imax[tid >> 5] = tmax;
    __syncthreads();
    if (tid < NTH / 32) {
        int v = s_imax[tid];
#pragma unroll
        for (int o = (NTH / 64); o > 0; o >>= 1)
            v = max(v, __shfl_down_sync((1u << (NTH / 32)) - 1u, v, o));
        if (tid == 0) g_tcut = v;
    }
}

// ---------------------------------------------------------------------------
__device__ __forceinline__ void load_chunk(float4 v[TCHUNK], const float4* __restrict__ u2v,
                                           int tstart, int b4, int T, int B) {
#pragma unroll
    for (int t = 0; t < TCHUNK; t++)
        v[t] = (tstart + t < T) ? u2v[((size_t)(tstart + t) * B + b4) >> 2]
                                : make_float4(0.f, 0.f, 0.f, 0.f);
}

__device__ __forceinline__ void process_chunk(const float4 v[TCHUNK], int tstart, int b4,
                                              const float* __restrict__ u1,
                                              const float* __restrict__ u2,
                                              float u2min, int T, int B) {
    unsigned m0 = 0, m1 = 0, m2 = 0, m3 = 0;
#pragma unroll
    for (int t = 0; t < TCHUNK; t++) {
        if (v[t].x > u2min) m0 |= 1u << t;
        if (v[t].y > u2min) m1 |= 1u << t;
        if (v[t].z > u2min) m2 |= 1u << t;
        if (v[t].w > u2min) m3 |= 1u << t;
    }
    const float EPSF = 1e-12f;
#pragma unroll
    for (int l = 0; l < 4; l++) {
        unsigned m = (l == 0) ? m0 : (l == 1) ? m1 : (l == 2) ? m2 : m3;
        if (m && (T - g_deathX[b4 + l]) > tstart) {     // not already dead earlier
            while (m) {
                int t = __ffs(m) - 1;
                m &= m - 1;
                size_t idx = (size_t)(tstart + t) * B + b4 + l;
                float la = __logf(u2[idx] + EPSF);
                float lb = __logf(u1[idx] + EPSF);
                if (la > g_T2[tstart + t] * lb) {
                    atomicMax(&g_deathX[b4 + l], T - (tstart + t));
                    break;              // bits ascend in t: first hit = chunk minimum
                }
            }
        }
    }
}

// ---------------------------------------------------------------------------
// Single fused kernel. Grid = (ceil(B/2048), GRIDY) = 148 blocks, 1 block/SM,
// all resident in wave 1 => internal flag-spins are deadlock-free.
__global__ void __launch_bounds__(NTH, 1)
k_all(const float* __restrict__ acts, const float* __restrict__ u1,
      const float* __restrict__ u2, float* __restrict__ out,
      int T, int B, int nelem, int nblocks) {
    int tid  = threadIdx.x;
    int flat = blockIdx.y * gridDim.x + blockIdx.x;
    bool producer = (flat == 0);

    // ---- Phase 1: wide coalesced elementwise + zero-pad (first nelem blocks) ----
    if (flat < nelem) {
        const float LOG_GAMMA_F = (float)log(1.02);
        int i = flat * NTH + tid;
        if (i < PADT) {
            float fv = 0.0f, cv = 0.0f;
            if (i < T) {
                fv = __expf(acts[i]);
                cv = LOG_GAMMA_F + __logf(1.0f - fv);
            }
            g_f[i] = fv;
            g_c[i] = cv;
        }
        __syncthreads();
        if (tid == 0) { __threadfence(); atomicAdd(&g_elemdone, 1); }
    }

    int b4 = (blockIdx.x * NTH + tid) * 4;
    bool lanes_ok = (b4 + 3 < B);
    const float4* u2v = (const float4*)u2;

    if (producer) {
        // ---- Phase 2: scan bases / thresholds / prefix (this block only) ----
        if (tid == 0) { while (atomicAdd(&g_elemdone, 0) < nelem) __nanosleep(64); }
        __syncthreads();
        __threadfence();
        scanbases_body(T);
        __syncthreads();
        if (tid == 0) { __threadfence(); atomicExch(&g_flag, 1); }
        __syncthreads();
        // ---- Phase 3 (producer's chunks, normal loads) ----
        int tcut = g_tcut;
        for (int chunk = blockIdx.y; chunk * TCHUNK < tcut; chunk += GRIDY) {
            if (lanes_ok) {
                float4 v[TCHUNK];
                load_chunk(v, u2v, chunk * TCHUNK, b4, T, B);
                process_chunk(v, chunk * TCHUNK, b4, u1, u2, g_u2min[chunk], T, B);
            }
        }
    } else {
        // ---- overlap: prefetch this block's first chunk while phase 2 runs ----
        float4 v[TCHUNK];
        int pchunk = blockIdx.y;
        if (lanes_ok) load_chunk(v, u2v, pchunk * TCHUNK, b4, T, B);
        if (tid == 0) {
            volatile int* vf = &g_flag;
            while (*vf == 0) __nanosleep(128);
        }
        __syncthreads();
        __threadfence();
        int tcut = g_tcut;
        if (lanes_ok && pchunk * TCHUNK < tcut)
            process_chunk(v, pchunk * TCHUNK, b4, u1, u2, g_u2min[pchunk], T, B);
        for (int chunk = pchunk + GRIDY; chunk * TCHUNK < tcut; chunk += GRIDY) {
            if (lanes_ok) {
                float4 w[TCHUNK];
                load_chunk(w, u2v, chunk * TCHUNK, b4, T, B);
                process_chunk(w, chunk * TCHUNK, b4, u1, u2, g_u2min[chunk], T, B);
            }
        }
    }

    // ---- Phase 4: last block reduces, then resets sync state for next replay ----
    __threadfence();
    __shared__ int lastFlag;
    if (tid == 0) lastFlag = (atomicAdd(&g_done, 1) == nblocks - 1);
    __syncthreads();
    if (!lastFlag) return;

    __shared__ double s_red[NTH / 32];
    double s = 0.0;
    for (int i = tid; i < B; i += NTH)
        s += g_prefix[T - g_deathX[i]];        // deathX=0 (alive) -> prefix[T]
#pragma unroll
    for (int o = 16; o > 0; o >>= 1) s += __shfl_down_sync(0xffffffffu, s, o);
    if ((tid & 31) == 0) s_red[tid >> 5] = s;
    __syncthreads();
    if (tid < NTH / 32) {
        double v = s_red[tid];
#pragma unroll
        for (int o = NTH / 64; o > 0; o >>= 1)
            v += __shfl_down_sync((1u << (NTH / 32)) - 1u, v, o);
        if (tid == 0) out[0] = (float)(v / (double)B);
    }
    __syncthreads();
    for (int i = tid; i < B; i += NTH) g_deathX[i] = 0;   // reset for next replay
    if (tid == 0) { g_flag = 0; g_elemdone = 0; g_done = 0; }
}

extern "C" void kernel_launch(void* const* d_in, const int* in_sizes, int n_in,
                              void* d_out, int out_size) {
    const float* acts = (const float*)d_in[0];
    const float* u1   = (const float*)d_in[1];
    const float* u2   = (const float*)d_in[2];
    int T = in_sizes[0];
    int B = (T > 0) ? (in_sizes[1] / T) : 0;

    int gx = (B + NTH * 4 - 1) / (NTH * 4);           // 2 for B=4096
    dim3 grid(gx, GRIDY);                             // 148 blocks total
    int nblocks = gx * GRIDY;
    int maxTB = (T > B) ? T : B;
    int nelem = (maxTB + NTH - 1) / NTH;              // 20
    k_all<<<grid, NTH>>>(acts, u1, u2, (float*)d_out, T, B, nelem, nblocks);
}

// round 13
// speedup vs baseline: 1.2746x; 1.0007x over previous
#include <cuda_runtime.h>
#include <math.h>
#include <stdint.h>

#define MAXT_C 10000
#define PADT   10240     // NTH * ELEMS, zero-padded so float4 reloads are unguarded
#define MAXB_C 4096
#define TCHUNK 16
#define NTH    512
#define ELEMS  20        // ceil(10000/512)
#define GRIDY  74        // persistent grid: 2 x 74 = 148 blocks = 1 wave @ 1 block/SM
#define KCAND  3
// Input-independent screen: T2_t <= T2_0 = q0/(1-q0) ~= 1.001e-3 (logp strictly
// decreases). Death needs la > T2*lb, lb >= log(1e-12) = -27.631:
// u2 > exp(-27.632*1.0011e-3) ~= 0.97271. 0.9720 is safely conservative.
#define U2MIN_GLOB 0.9720f

// Scratch (static __device__ arrays: no allocation allowed)
__device__ float   g_f[PADT];            // exp(acts[t]), zero past T
__device__ float   g_c[PADT];            // LOG_GAMMA + log(1 - f), zero past T
__device__ __align__(16) float g_T2[MAXT_C + TCHUNK];  // thresholds (padded row reads OK)
__device__ double  g_prefix[MAXT_C + 1]; // prefix[k] = sum_{t<k} w_t
__device__ int     g_deathX[MAXB_C];     // atomicMax of (T - death_t); 0 = alive (zero-init OK)
__device__ int     g_tcut;               // no deaths possible for t >= g_tcut
__device__ int     g_elemdone;           // phase-1 counter      (reset by last block)
__device__ int     g_flag;               // phase-2 publication  (reset by last block)
__device__ int     g_done8[8];           // level-1 arrival      (reset by last block)
__device__ int     g_done;               // level-2 arrival      (reset by last block)

// ---------------------------------------------------------------------------
__device__ __forceinline__ float block_scan_excl_f32(float v, float& total, float* s_warp) {
    const unsigned FULL = 0xffffffffu;
    int lane = threadIdx.x & 31;
    int w    = threadIdx.x >> 5;
    const int NW = NTH / 32;
    float inc = v;
#pragma unroll
    for (int o = 1; o < 32; o <<= 1) {
        float n = __shfl_up_sync(FULL, inc, o);
        if (lane >= o) inc += n;
    }
    float exc = __shfl_up_sync(FULL, inc, 1);
    if (lane == 0) exc = 0.0f;
    if (lane == 31) s_warp[w] = inc;
    __syncthreads();
    if (w == 0 && lane < NW) {
        float i2 = s_warp[lane];
#pragma unroll
        for (int o = 1; o < NW; o <<= 1) {
            float n = __shfl_up_sync((1u << NW) - 1u, i2, o);
            if (lane >= o) i2 += n;
        }
        float e2 = __shfl_up_sync((1u << NW) - 1u, i2, 1);
        if (lane == 0) e2 = 0.0f;
        s_warp[lane] = e2;
        if (lane == NW - 1) s_warp[NW] = i2;
    }
    __syncthreads();
    exc += s_warp[w];
    total = s_warp[NW];
    __syncthreads();
    return exc;
}

__device__ __forceinline__ double block_scan_excl_f64(double v, double& total, double* s_warp) {
    const unsigned FULL = 0xffffffffu;
    int lane = threadIdx.x & 31;
    int w    = threadIdx.x >> 5;
    const int NW = NTH / 32;
    double inc = v;
#pragma unroll
    for (int o = 1; o < 32; o <<= 1) {
        double n = __shfl_up_sync(FULL, inc, o);
        if (lane >= o) inc += n;
    }
    double exc = __shfl_up_sync(FULL, inc, 1);
    if (lane == 0) exc = 0.0;
    if (lane == 31) s_warp[w] = inc;
    __syncthreads();
    if (w == 0 && lane < NW) {
        double i2 = s_warp[lane];
#pragma unroll
        for (int o = 1; o < NW; o <<= 1) {
            double n = __shfl_up_sync((1u << NW) - 1u, i2, o);
            if (lane >= o) i2 += n;
        }
        double e2 = __shfl_up_sync((1u << NW) - 1u, i2, 1);
        if (lane == 0) e2 = 0.0;
        s_warp[lane] = e2;
        if (lane == NW - 1) s_warp[NW] = i2;
    }
    __syncthreads();
    exc += s_warp[w];
    total = s_warp[NW];
    __syncthreads();
    return exc;
}

__device__ __forceinline__ float exp_tiny(float x) {
    if (fabsf(x) < 0.03f)
        return 1.0f + x * (1.0f + x * (0.5f + x * (1.0f / 6.0f)));
    return __expf(x);
}

// ---------------------------------------------------------------------------
// Phase 2 body (producer block only). fp32 W/P scans, fp64 S scan; no arrays.
__device__ void scanbases_body(int T) {
    __shared__ float  s_warpf[NTH / 32 + 1];
    __shared__ double s_warpd[NTH / 32 + 1];
    __shared__ int s_imax[NTH / 32];
    int tid = threadIdx.x;
    int seg = tid * ELEMS;
    const float4* f4 = (const float4*)g_f;
    const float4* c4 = (const float4*)g_c;

    const float ALPHA_F     = (float)(log(0.99) / 1000.0);
    const float INIT_LOGW_F = (float)log(0.248);
    const float INIT_LOGP_F = (float)log(0.001);

    float csum = 0.0f;
#pragma unroll
    for (int k = 0; k < ELEMS / 4; k++) {
        float4 c = c4[(seg >> 2) + k];
        csum += c.x + c.y + c.z + c.w;
    }
    float ctot;
    float Wbase = block_scan_excl_f32(csum, ctot, s_warpf) + INIT_LOGW_F;

    float dfsum = 0.0f;
    {
        float ew = __expf(Wbase);
#pragma unroll
        for (int k = 0; k < ELEMS / 4; k++) {
            float4 f = f4[(seg >> 2) + k];
            dfsum += ALPHA_F * f.x * ew; ew *= 1.02f * (1.0f - f.x);
            dfsum += ALPHA_F * f.y * ew; ew *= 1.02f * (1.0f - f.y);
            dfsum += ALPHA_F * f.z * ew; ew *= 1.02f * (1.0f - f.z);
            dfsum += ALPHA_F * f.w * ew; ew *= 1.02f * (1.0f - f.w);
        }
    }
    float dtot;
    float Pbase = block_scan_excl_f32(dfsum, dtot, s_warpf) + INIT_LOGP_F;

    float wvsum = 0.0f;
    int tmax = 0;
    {
        float ew = __expf(Wbase);
        float q  = __expf(Pbase);
        float v  = __expf(Wbase * 0.001f);
#pragma unroll
        for (int k = 0; k < ELEMS / 4; k++) {
            float4 f = f4[(seg >> 2) + k];
            float4 c = c4[(seg >> 2) + k];
#pragma unroll
            for (int u = 0; u < 4; u++) {
                float fe = (u == 0) ? f.x : (u == 1) ? f.y : (u == 2) ? f.z : f.w;
                float ce = (u == 0) ? c.x : (u == 1) ? c.y : (u == 2) ? c.z : c.w;
                int i = seg + k * 4 + u;
                v *= exp_tiny(ce * 0.001f);
                if (i < T) {
                    float thr = q * (1.0f + q + q * q);     // = q/(1-q), q <= 1e-3
                    g_T2[i] = thr - 1e-12f;
                    if (q >= 1.4e-11f) tmax = i + 1;        // logit >= -25 (noise <= ~20)
                    wvsum += v;
                }
                float df = ALPHA_F * fe * ew;
                q = (q >= 1e-13f) ? q * exp_tiny(df) : 0.0f;
                ew *= 1.02f * (1.0f - fe);
            }
        }
    }
    double tot;
    double Sbase = block_scan_excl_f64((double)wvsum, tot, s_warpd);
    {
        float v = __expf(Wbase * 0.001f);
        float ls = 0.0f;
#pragma unroll
        for (int k = 0; k < ELEMS / 4; k++) {
            float4 c = c4[(seg >> 2) + k];
#pragma unroll
            for (int u = 0; u < 4; u++) {
                float ce = (u == 0) ? c.x : (u == 1) ? c.y : (u == 2) ? c.z : c.w;
                int i = seg + k * 4 + u;
                v *= exp_tiny(ce * 0.001f);
                if (i < T) {
                    g_prefix[i] = Sbase + (double)ls;
                    ls += v;
                }
            }
        }
    }
    if (tid == 0) g_prefix[T] = tot;

#pragma unroll
    for (int o = 16; o > 0; o >>= 1) tmax = max(tmax, __shfl_down_sync(0xffffffffu, tmax, o));
    if ((tid & 31) == 0) s_imax[tid >> 5] = tmax;
    __syncthreads();
    if (tid < NTH / 32) {
        int v = s_imax[tid];
#pragma unroll
        for (int o = (NTH / 64); o > 0; o >>= 1)
            v = max(v, __shfl_down_sync((1u << (NTH / 32)) - 1u, v, o));
        if (tid == 0) g_tcut = v;
    }
}

// ---------------------------------------------------------------------------
// Cold full resolution of a chunk (producer's chunk / rare tail chunks).
__device__ void resolve_cold(int tstart, int b4, const float* __restrict__ u1,
                             const float* __restrict__ u2, int T, int B) {
    const float4* u2v = (const float4*)u2;
    float4 v[TCHUNK];
#pragma unroll
    for (int t = 0; t < TCHUNK; t++)
        v[t] = (tstart + t < T) ? u2v[((size_t)(tstart + t) * B + b4) >> 2]
                                : make_float4(0.f, 0.f, 0.f, 0.f);
    unsigned m[4] = {0, 0, 0, 0};
#pragma unroll
    for (int t = 0; t < TCHUNK; t++) {
        if (v[t].x > U2MIN_GLOB) m[0] |= 1u << t;
        if (v[t].y > U2MIN_GLOB) m[1] |= 1u << t;
        if (v[t].z > U2MIN_GLOB) m[2] |= 1u << t;
        if (v[t].w > U2MIN_GLOB) m[3] |= 1u << t;
    }
    const float EPSF = 1e-12f;
#pragma unroll
    for (int l = 0; l < 4; l++) {
        unsigned mm = m[l];
        while (mm) {
            int t = __ffs(mm) - 1;
            mm &= mm - 1;
            size_t idx = (size_t)(tstart + t) * B + b4 + l;
            float la = __logf(u2[idx] + EPSF);
            float lb = __logf(u1[idx] + EPSF);
            float rc = (lb < 0.0f) ? __fdividef(la, lb) : 1e30f;
            if (rc < g_T2[tstart + t]) {
                atomicMax(&g_deathX[b4 + l], T - (tstart + t));
                break;
            }
        }
    }
}

// ---------------------------------------------------------------------------
__global__ void __launch_bounds__(NTH, 1)
k_all(const float* __restrict__ acts, const float* __restrict__ u1,
      const float* __restrict__ u2, float* __restrict__ out,
      int T, int B, int nelem, int nblocks) {
    int tid  = threadIdx.x;
    int flat = blockIdx.y * gridDim.x + blockIdx.x;
    bool producer = (flat == 0);
    // chunk remap: producer-row blocks (y=0) take the LAST chunk (likely > tcut);
    // consumers y>=1 take chunk y-1. Tail loop (+GRIDY) keeps full coverage.
    int cchunk = (blockIdx.y == 0) ? (GRIDY - 1) : (blockIdx.y - 1);
    int tstart = cchunk * TCHUNK;
    int b4 = (blockIdx.x * NTH + tid) * 4;
    bool lanes_ok = (b4 + 3 < B);
    const float4* u2v = (const float4*)u2;
    const float EPSF = 1e-12f;

    // ---- Phase 1: wide coalesced elementwise + zero-pad (first nelem blocks) ----
    if (flat < nelem) {
        const float LOG_GAMMA_F = (float)log(1.02);
        int i = flat * NTH + tid;
        if (i < PADT) {
            float fv = 0.0f, cv = 0.0f;
            if (i < T) {
                fv = __expf(acts[i]);
                cv = LOG_GAMMA_F + __logf(1.0f - fv);
            }
            g_f[i] = fv;
            g_c[i] = cv;
        }
        __syncthreads();
        if (tid == 0) { __threadfence(); atomicAdd(&g_elemdone, 1); }
    }

    __shared__ float s_T2f[TCHUNK];

    if (producer) {
        // ---- Phase 2 ----
        if (tid == 0) { while (atomicAdd(&g_elemdone, 0) < nelem) __nanosleep(64); }
        __syncthreads();
        __threadfence();
        scanbases_body(T);
        __syncthreads();
        if (tid == 0) { __threadfence(); atomicExch(&g_flag, 1); }
        __syncthreads();
        int tcut = g_tcut;
        for (int chunk = cchunk; chunk * TCHUNK < tcut; chunk += GRIDY)
            if (lanes_ok) resolve_cold(chunk * TCHUNK, b4, u1, u2, T, B);
    } else {
        // ---- Pre-flag (overlapped with phase 2): load, constant-screen,
        //      capture first KCAND candidates/lane, precompute rc ----
        int cnt[4] = {0, 0, 0, 0};
        int ct[4][KCAND];
        float cu[4][KCAND];
        if (lanes_ok) {
            float4 v[TCHUNK];
#pragma unroll
            for (int t = 0; t < TCHUNK; t++)
                v[t] = (tstart + t < T) ? u2v[((size_t)(tstart + t) * B + b4) >> 2]
                                        : make_float4(0.f, 0.f, 0.f, 0.f);
#pragma unroll
            for (int t = 0; t < TCHUNK; t++) {
#pragma unroll
                for (int l = 0; l < 4; l++) {
                    float uv = (l == 0) ? v[t].x : (l == 1) ? v[t].y : (l == 2) ? v[t].z : v[t].w;
                    if (uv > U2MIN_GLOB) {
                        int n = cnt[l];
                        if (n == 0)      { ct[l][0] = t; cu[l][0] = uv; }
                        else if (n == 1) { ct[l][1] = t; cu[l][1] = uv; }
                        else if (n == 2) { ct[l][2] = t; cu[l][2] = uv; }
                        cnt[l] = n + 1;
                    }
                }
            }
        }
        float crc[4][KCAND];
#pragma unroll
        for (int l = 0; l < 4; l++) {
#pragma unroll
            for (int k = 0; k < KCAND; k++) {
                if (cnt[l] > k) {
                    size_t idx = (size_t)(tstart + ct[l][k]) * B + b4 + l;
                    float u1v = u1[idx];
                    float la = __logf(cu[l][k] + EPSF);
                    float lb = __logf(u1v + EPSF);
                    crc[l][k] = (lb < 0.0f) ? __fdividef(la, lb) : 1e30f;
                }
            }
        }
        // ---- Flag wait ----
        if (tid == 0) {
            volatile int* vf = &g_flag;
            while (*vf == 0) __nanosleep(64);
        }
        __syncthreads();
        __threadfence();
        // ---- Post-flag: compares only ----
        int tcut = g_tcut;
        if (tstart < tcut) {
            if (tid < TCHUNK / 4)
                ((float4*)s_T2f)[tid] = ((const float4*)(g_T2 + tstart))[tid];
            __syncthreads();
            if (lanes_ok) {
#pragma unroll
                for (int l = 0; l < 4; l++) {
                    int death_t = -1;
#pragma unroll
                    for (int k = 0; k < KCAND; k++) {
                        if (death_t < 0 && cnt[l] > k && crc[l][k] < s_T2f[ct[l][k]])
                            death_t = ct[l][k];
                    }
                    if (death_t < 0 && cnt[l] > KCAND) {
                        // rare fallback: rescan past the KCAND-th candidate
                        for (int t = ct[l][KCAND - 1] + 1; t < TCHUNK; t++) {
                            size_t idx = (size_t)(tstart + t) * B + b4 + l;
                            float uv = u2[idx];
                            if (uv > U2MIN_GLOB) {
                                float la = __logf(uv + EPSF);
                                float lb = __logf(u1[idx] + EPSF);
                                float rc = (lb < 0.0f) ? __fdividef(la, lb) : 1e30f;
                                if (rc < s_T2f[t]) { death_t = t; break; }
                            }
                        }
                    }
                    if (death_t >= 0)
                        atomicMax(&g_deathX[b4 + l], T - (tstart + death_t));
                }
            }
        }
        for (int chunk = cchunk + GRIDY; chunk * TCHUNK < tcut; chunk += GRIDY)
            if (lanes_ok) resolve_cold(chunk * TCHUNK, b4, u1, u2, T, B);
    }

    // ---- Completion: two-level arrival; final arriver reduces + resets ----
    __shared__ int lastFlag;
    if (tid == 0) {
        __threadfence();
        int bucket = flat & 7;
        int quota = (nblocks - bucket + 7) >> 3;     // #flats == bucket (mod 8)
        int lf = 0;
        if (atomicAdd(&g_done8[bucket], 1) == quota - 1)
            lf = (atomicAdd(&g_done, 1) == 7);
        lastFlag = lf;
    }
    __syncthreads();
    if (!lastFlag) return;

    __shared__ double s_red[NTH / 32];
    double s = 0.0;
    for (int i = tid; i < B; i += NTH)
        s += g_prefix[T - g_deathX[i]];              // deathX=0 (alive) -> prefix[T]
#pragma unroll
    for (int o = 16; o > 0; o >>= 1) s += __shfl_down_sync(0xffffffffu, s, o);
    if ((tid & 31) == 0) s_red[tid >> 5] = s;
    __syncthreads();
    if (tid < NTH / 32) {
        double v = s_red[tid];
#pragma unroll
        for (int o = NTH / 64; o > 0; o >>= 1)
            v += __shfl_down_sync((1u << (NTH / 32)) - 1u, v, o);
        if (tid == 0) out[0] = (float)(v / (double)B);
    }
    __syncthreads();
    for (int i = tid; i < B; i += NTH) g_deathX[i] = 0;   // reset for next replay
    if (tid < 8) g_done8[tid] = 0;
    if (tid == 0) { g_flag = 0; g_elemdone = 0; g_done = 0; }
}

extern "C" void kernel_launch(void* const* d_in, const int* in_sizes, int n_in,
                              void* d_out, int out_size) {
    const float* acts = (const float*)d_in[0];
    const float* u1   = (const float*)d_in[1];
    const float* u2   = (const float*)d_in[2];
    int T = in_sizes[0];
    int B = (T > 0) ? (in_sizes[1] / T) : 0;

    int gx = (B + NTH * 4 - 1) / (NTH * 4);           // 2 for B=4096
    dim3 grid(gx, GRIDY);                             // 148 blocks total
    int nblocks = gx * GRIDY;
    int maxTB = (T > B) ? T : B;
    int nelem = (maxTB + NTH - 1) / NTH;              // 20
    k_all<<<grid, NTH>>>(acts, u1, u2, (float*)d_out, T, B, nelem, nblocks);
}

// round 14
// speedup vs baseline: 1.3887x; 1.0895x over previous
#include <cuda_runtime.h>
#include <math.h>
#include <stdint.h>

#define MAXT_C 10000
#define NTH    640
#define ELEMS  16
#define PADT   (NTH * ELEMS)   // 10240
#define NSEG   NTH             // 640 segments of 16
#define MAXB_C 4096
#define TCHUNK 16
#define GRIDY  74              // 2 x 74 = 148 blocks = 1 wave @ 1 block/SM
#define KCAND  3
#define NW     (NTH / 32)      // 20
#define FULLM  0xffffffffu
// Input-independent screen: T2_t <= q0/(1-q0) ~= 1.001e-3; death needs
// u2 > exp(log(1e-12)*T2_0) ~= 0.97271. 0.9720 is safely conservative.
#define U2MIN_GLOB 0.9720f

// Scratch (static __device__ arrays: no allocation allowed)
__device__ float   g_f[PADT];          // exp(acts[t]), zero past T
__device__ float   g_c[PADT];          // LOG_GAMMA + log(1 - f), zero past T
__device__ float4  g_segpart[NSEG];    // per-segment (csum, R, V, 0)
__device__ float2  g_wq[NSEG];         // per-segment (Wbase, qbase)
__device__ double  g_prefix[MAXT_C + 1];
__device__ int     g_deathX[MAXB_C];   // atomicMax of (T - death_t); 0 = alive (zero-init OK)
__device__ int     g_elemdone;         // phase-1 counter        (reset by last block)
__device__ int     g_flag;             // tcut+1 when published  (reset by last block)
__device__ int     g_done8[8];         // level-1 arrival        (reset by last block)
__device__ int     g_done;             // level-2 arrival        (reset by last block)

// ---------------------------------------------------------------------------
__device__ __forceinline__ float block_scan_excl_f32(float v, float& total, float* s_warp) {
    int lane = threadIdx.x & 31, w = threadIdx.x >> 5;
    float inc = v;
#pragma unroll
    for (int o = 1; o < 32; o <<= 1) { float n = __shfl_up_sync(FULLM, inc, o); if (lane >= o) inc += n; }
    float exc = __shfl_up_sync(FULLM, inc, 1);
    if (lane == 0) exc = 0.f;
    if (lane == 31) s_warp[w] = inc;
    __syncthreads();
    if (w == 0) {
        float i2 = (lane < NW) ? s_warp[lane] : 0.f;
#pragma unroll
        for (int o = 1; o < 32; o <<= 1) { float n = __shfl_up_sync(FULLM, i2, o); if (lane >= o) i2 += n; }
        float e2 = __shfl_up_sync(FULLM, i2, 1);
        if (lane == 0) e2 = 0.f;
        if (lane < NW) s_warp[lane] = e2;
        if (lane == 31) s_warp[NW] = i2;
    }
    __syncthreads();
    exc += s_warp[w];
    total = s_warp[NW];
    __syncthreads();
    return exc;
}

__device__ __forceinline__ double block_scan_excl_f64(double v, double& total, double* s_warp) {
    int lane = threadIdx.x & 31, w = threadIdx.x >> 5;
    double inc = v;
#pragma unroll
    for (int o = 1; o < 32; o <<= 1) { double n = __shfl_up_sync(FULLM, inc, o); if (lane >= o) inc += n; }
    double exc = __shfl_up_sync(FULLM, inc, 1);
    if (lane == 0) exc = 0.0;
    if (lane == 31) s_warp[w] = inc;
    __syncthreads();
    if (w == 0) {
        double i2 = (lane < NW) ? s_warp[lane] : 0.0;
#pragma unroll
        for (int o = 1; o < 32; o <<= 1) { double n = __shfl_up_sync(FULLM, i2, o); if (lane >= o) i2 += n; }
        double e2 = __shfl_up_sync(FULLM, i2, 1);
        if (lane == 0) e2 = 0.0;
        if (lane < NW) s_warp[lane] = e2;
        if (lane == 31) s_warp[NW] = i2;
    }
    __syncthreads();
    exc += s_warp[w];
    total = s_warp[NW];
    __syncthreads();
    return exc;
}

__device__ __forceinline__ float exp_tiny(float x) {
    if (fabsf(x) < 0.03f)
        return 1.0f + x * (1.0f + x * (0.5f + x * (1.0f / 6.0f)));
    return __expf(x);
}

// ---------------------------------------------------------------------------
// Compute the 16 T2 thresholds of segment `seg` into s_T2f (warp 0 only; the
// caller must __syncthreads() before using s_T2f).
__device__ __forceinline__ void compute_T2_smem(int seg, float* s_T2f) {
    if (threadIdx.x < 32) {
        const float ALPHA_F = (float)(log(0.99) / 1000.0);
        int half = threadIdx.x & 15;
        float2 wq = g_wq[seg];
        float fe = g_f[seg * 16 + half];
        float ce = g_c[seg * 16 + half];
        float inc = ce;                               // inclusive scan of c, width 16
#pragma unroll
        for (int o = 1; o < 16; o <<= 1) { float n = __shfl_up_sync(FULLM, inc, o, 16); if (half >= o) inc += n; }
        float rt = fe * __expf(inc - ce);             // f_j * e^{localW_j}
        float rinc = rt;
#pragma unroll
        for (int o = 1; o < 16; o <<= 1) { float n = __shfl_up_sync(FULLM, rinc, o, 16); if (half >= o) rinc += n; }
        float rexc = rinc - rt;                       // sum_{k<j} f_k e^{localW_k}
        float q = wq.y * __expf(ALPHA_F * __expf(wq.x) * rexc);
        if (threadIdx.x < 16) s_T2f[half] = q * (1.0f + q + q * q) - 1e-12f;
    }
}

// Cold full resolution of one chunk against s_T2f (any thread subset).
__device__ void cold_resolve(int tstart, int b4, const float* __restrict__ u1,
                             const float* __restrict__ u2, int T, int B,
                             const float* s_T2f) {
    const float4* u2v = (const float4*)u2;
    float4 v[TCHUNK];
#pragma unroll
    for (int t = 0; t < TCHUNK; t++)
        v[t] = (tstart + t < T) ? u2v[((size_t)(tstart + t) * B + b4) >> 2]
                                : make_float4(0.f, 0.f, 0.f, 0.f);
    unsigned m[4] = {0, 0, 0, 0};
#pragma unroll
    for (int t = 0; t < TCHUNK; t++) {
        if (v[t].x > U2MIN_GLOB) m[0] |= 1u << t;
        if (v[t].y > U2MIN_GLOB) m[1] |= 1u << t;
        if (v[t].z > U2MIN_GLOB) m[2] |= 1u << t;
        if (v[t].w > U2MIN_GLOB) m[3] |= 1u << t;
    }
    const float EPSF = 1e-12f;
#pragma unroll
    for (int l = 0; l < 4; l++) {
        unsigned mm = m[l];
        while (mm) {
            int t = __ffs(mm) - 1;
            mm &= mm - 1;
            size_t idx = (size_t)(tstart + t) * B + b4 + l;
            float la = __logf(u2[idx] + EPSF);
            float lb = __logf(u1[idx] + EPSF);
            float rc = (lb < 0.0f) ? __fdividef(la, lb) : 1e30f;
            if (rc < s_T2f[t]) {
                atomicMax(&g_deathX[b4 + l], T - (tstart + t));
                break;
            }
        }
    }
}

// ---------------------------------------------------------------------------
__global__ void __launch_bounds__(NTH, 1)
k_all(const float* __restrict__ acts, const float* __restrict__ u1,
      const float* __restrict__ u2, float* __restrict__ out,
      int T, int B, int nelem, int nblocks) {
    int tid  = threadIdx.x;
    int flat = blockIdx.y * gridDim.x + blockIdx.x;
    bool producer = (flat == 0);
    int cchunk = (blockIdx.y == 0) ? (GRIDY - 1) : (blockIdx.y - 1);
    int tstart = cchunk * TCHUNK;
    int b4 = (blockIdx.x * NTH + tid) * 4;
    bool lanes_ok = (b4 + 3 < B);
    const float4* u2v = (const float4*)u2;
    const float EPSF = 1e-12f;
    const float LOG_GAMMA_F = (float)log(1.02);
    const float ALPHA_F     = (float)(log(0.99) / 1000.0);
    const float INIT_LOGW_F = (float)log(0.248);
    const float INIT_LOGP_F = (float)log(0.001);

    __shared__ float  s_T2f[TCHUNK];
    __shared__ float  s_warpf[NW + 1];
    __shared__ double s_warpd[NW + 1];
    __shared__ int    s_ired[NW];
    __shared__ int    s_tcut;
    __shared__ int    lastFlag;

    // ---- Phase 1: elementwise + per-segment partials (first nelem blocks) ----
    if (flat < nelem) {
        int i = flat * NTH + tid;
        int half = tid & 15;
        float fv = 0.f, cv = 0.f;
        if (i < T) { fv = __expf(acts[i]); cv = LOG_GAMMA_F + __logf(1.f - fv); }
        if (i < PADT) { g_f[i] = fv; g_c[i] = cv; }
        float inc = cv;                               // inclusive scan of c, width 16
#pragma unroll
        for (int o = 1; o < 16; o <<= 1) { float n = __shfl_up_sync(FULLM, inc, o, 16); if (half >= o) inc += n; }
        float rt = (i < T) ? fv * __expf(inc - cv) : 0.f;   // f_j e^{localW_j}
        float vt = (i < T) ? __expf(inc * 0.001f) : 0.f;    // e^{localW_{j+1}/1000}
        float rs = rt, vs = vt;
#pragma unroll
        for (int o = 8; o > 0; o >>= 1) {
            rs += __shfl_xor_sync(FULLM, rs, o, 16);
            vs += __shfl_xor_sync(FULLM, vs, o, 16);
        }
        float cs = __shfl_sync(FULLM, inc, 15, 16);
        if (half == 0 && i < PADT) g_segpart[i >> 4] = make_float4(cs, rs, vs, 0.f);
        __syncthreads();
        if (tid == 0) { __threadfence(); atomicAdd(&g_elemdone, 1); }
    }

    if (producer) {
        // ---- Producer: minimal pre-flag path ----
        if (tid == 0) { while (atomicAdd(&g_elemdone, 0) < nelem) __nanosleep(64); }
        __syncthreads();
        __threadfence();
        float4 sp = g_segpart[tid];
        float ctot;
        float Wbase = block_scan_excl_f32(sp.x, ctot, s_warpf) + INIT_LOGW_F;
        float dfs = ALPHA_F * sp.y * __expf(Wbase);
        float dtot;
        float Pbase = block_scan_excl_f32(dfs, dtot, s_warpf) + INIT_LOGP_F;
        float qbase = __expf(Pbase);
        g_wq[tid] = make_float2(Wbase, qbase);
        // tcut = 16 * (1 + highest segment with qbase >= 1.4e-11)
        unsigned bal = __ballot_sync(FULLM, qbase >= 1.4e-11f);
        int lane = tid & 31, w = tid >> 5;
        int wmax = bal ? (w * 32 + (31 - __clz(bal)) + 1) : 0;
        if (lane == 0) s_ired[w] = wmax;
        __syncthreads();
        if (tid < 32) {
            int vv = (tid < NW) ? s_ired[tid] : 0;
#pragma unroll
            for (int o = 16; o > 0; o >>= 1) vv = max(vv, __shfl_down_sync(FULLM, vv, o));
            if (tid == 0) {
                s_tcut = vv * TCHUNK;
                __threadfence();
                atomicExch(&g_flag, vv * TCHUNK + 1);   // publish EARLY
            }
        }
        __syncthreads();
        // ---- Post-flag (overlaps consumers): S scan + prefix writes ----
        float wvs = sp.z * __expf(Wbase * 0.001f);
        double tot;
        double Sbase = block_scan_excl_f64((double)wvs, tot, s_warpd);
        {
            const float4* c4 = (const float4*)g_c;
            float v = __expf(Wbase * 0.001f);
            float ls = 0.f;
#pragma unroll
            for (int k = 0; k < 4; k++) {
                float4 c = c4[tid * 4 + k];
#pragma unroll
                for (int u = 0; u < 4; u++) {
                    float ce = (u == 0) ? c.x : (u == 1) ? c.y : (u == 2) ? c.z : c.w;
                    int i = tid * 16 + k * 4 + u;
                    v *= exp_tiny(ce * 0.001f);
                    if (i < T) { g_prefix[i] = Sbase + (double)ls; ls += v; }
                }
            }
        }
        if (tid == 0) g_prefix[T] = tot;
        // generic tail (never runs for this shape)
        int tcut = s_tcut;
        for (int chunk = cchunk; chunk * TCHUNK < tcut; chunk += GRIDY) {
            __syncthreads();
            compute_T2_smem(chunk, s_T2f);
            __syncthreads();
            if (lanes_ok) cold_resolve(chunk * TCHUNK, b4, u1, u2, T, B, s_T2f);
        }
    } else {
        // ---- Consumer pre-flag (overlapped): screen + candidate rc ----
        int cnt[4] = {0, 0, 0, 0};
        int ct[4][KCAND];
        float cu[4][KCAND];
        if (lanes_ok) {
            float4 v[TCHUNK];
#pragma unroll
            for (int t = 0; t < TCHUNK; t++)
                v[t] = (tstart + t < T) ? u2v[((size_t)(tstart + t) * B + b4) >> 2]
                                        : make_float4(0.f, 0.f, 0.f, 0.f);
#pragma unroll
            for (int t = 0; t < TCHUNK; t++) {
#pragma unroll
                for (int l = 0; l < 4; l++) {
                    float uv = (l == 0) ? v[t].x : (l == 1) ? v[t].y : (l == 2) ? v[t].z : v[t].w;
                    if (uv > U2MIN_GLOB) {
                        int n = cnt[l];
                        if (n == 0)      { ct[l][0] = t; cu[l][0] = uv; }
                        else if (n == 1) { ct[l][1] = t; cu[l][1] = uv; }
                        else if (n == 2) { ct[l][2] = t; cu[l][2] = uv; }
                        cnt[l] = n + 1;
                    }
                }
            }
        }
        float crc[4][KCAND];
#pragma unroll
        for (int l = 0; l < 4; l++) {
#pragma unroll
            for (int k = 0; k < KCAND; k++) {
                if (cnt[l] > k) {
                    size_t idx = (size_t)(tstart + ct[l][k]) * B + b4 + l;
                    float la = __logf(cu[l][k] + EPSF);
                    float lb = __logf(u1[idx] + EPSF);
                    crc[l][k] = (lb < 0.0f) ? __fdividef(la, lb) : 1e30f;
                }
            }
        }
        // ---- Flag wait (value = tcut + 1) ----
        if (tid == 0) {
            volatile int* vf = &g_flag;
            int fv;
            while ((fv = *vf) == 0) __nanosleep(64);
            s_tcut = fv - 1;
        }
        __syncthreads();
        __threadfence();
        int tcut = s_tcut;
        bool active = (tstart < tcut);
        if (active) compute_T2_smem(cchunk, s_T2f);
        __syncthreads();
        if (active && lanes_ok) {
#pragma unroll
            for (int l = 0; l < 4; l++) {
                int death_t = -1;
#pragma unroll
                for (int k = 0; k < KCAND; k++) {
                    if (death_t < 0 && cnt[l] > k && crc[l][k] < s_T2f[ct[l][k]])
                        death_t = ct[l][k];
                }
                if (death_t < 0 && cnt[l] > KCAND) {
                    for (int t = ct[l][KCAND - 1] + 1; t < TCHUNK; t++) {
                        size_t idx = (size_t)(tstart + t) * B + b4 + l;
                        float uv = u2[idx];
                        if (uv > U2MIN_GLOB) {
                            float la = __logf(uv + EPSF);
                            float lb = __logf(u1[idx] + EPSF);
                            float rc = (lb < 0.0f) ? __fdividef(la, lb) : 1e30f;
                            if (rc < s_T2f[t]) { death_t = t; break; }
                        }
                    }
                }
                if (death_t >= 0)
                    atomicMax(&g_deathX[b4 + l], T - (tstart + death_t));
            }
        }
        // generic tail (never runs for this shape)
        for (int chunk = cchunk + GRIDY; chunk * TCHUNK < tcut; chunk += GRIDY) {
            __syncthreads();
            compute_T2_smem(chunk, s_T2f);
            __syncthreads();
            if (lanes_ok) cold_resolve(chunk * TCHUNK, b4, u1, u2, T, B, s_T2f);
        }
    }

    // ---- Completion: two-level arrival; final arriver reduces + resets ----
    if (tid == 0) {
        __threadfence();
        int bucket = flat & 7;
        int quota = (nblocks - bucket + 7) >> 3;
        int lf = 0;
        if (atomicAdd(&g_done8[bucket], 1) == quota - 1)
            lf = (atomicAdd(&g_done, 1) == 7);
        lastFlag = lf;
    }
    __syncthreads();
    if (!lastFlag) return;

    __shared__ double s_red[NW];
    double s = 0.0;
    for (int i = tid; i < B; i += NTH)
        s += g_prefix[T - g_deathX[i]];              // deathX=0 (alive) -> prefix[T]
#pragma unroll
    for (int o = 16; o > 0; o >>= 1) s += __shfl_down_sync(FULLM, s, o);
    if ((tid & 31) == 0) s_red[tid >> 5] = s;
    __syncthreads();
    if (tid < 32) {
        double v = (tid < NW) ? s_red[tid] : 0.0;
#pragma unroll
        for (int o = 16; o > 0; o >>= 1) v += __shfl_down_sync(FULLM, v, o);
        if (tid == 0) out[0] = (float)(v / (double)B);
    }
    __syncthreads();
    for (int i = tid; i < B; i += NTH) g_deathX[i] = 0;   // reset for next replay
    if (tid < 8) g_done8[tid] = 0;
    if (tid == 0) { g_flag = 0; g_elemdone = 0; g_done = 0; }
}

extern "C" void kernel_launch(void* const* d_in, const int* in_sizes, int n_in,
                              void* d_out, int out_size) {
    const float* acts = (const float*)d_in[0];
    const float* u1   = (const float*)d_in[1];
    const float* u2   = (const float*)d_in[2];
    int T = in_sizes[0];
    int B = (T > 0) ? (in_sizes[1] / T) : 0;

    int gx = (B + NTH * 4 - 1) / (NTH * 4);           // 2 for B=4096
    dim3 grid(gx, GRIDY);                             // 148 blocks total
    int nblocks = gx * GRIDY;
    int nelem = PADT / NTH;                           // 16
    k_all<<<grid, NTH>>>(acts, u1, u2, (float*)d_out, T, B, nelem, nblocks);
}